// round 10
// baseline (speedup 1.0000x reference)
#include <cuda_runtime.h>
#include <cuda_bf16.h>
#include <math.h>
#include <stdint.h>

#define Bb 8
#define Ss 256
#define Tt 32
#define Dd 512
#define NROWS 2048   // B*S
#define MROWS 256    // B*T

// Scratch (allocation-free rule: __device__ globals)
__device__ float g_H[NROWS * Dd];
__device__ float g_F[NROWS * Dd];
__device__ float g_A[MROWS * Dd];
__device__ float g_C[MROWS * Dd];

// ---------------------------------------------------------------------------
// Warp-MMA helpers (baseline PTX, compiles for plain sm_103)
// ---------------------------------------------------------------------------
__device__ __forceinline__ uint32_t smem_to_u32(const void* p) {
    uint32_t a;
    asm("{ .reg .u64 t; cvta.to.shared.u64 t, %1; cvt.u32.u64 %0, t; }"
        : "=r"(a) : "l"(p));
    return a;
}
__device__ __forceinline__ void ldsm_x4(uint32_t* r, uint32_t addr) {
    asm volatile("ldmatrix.sync.aligned.m8n8.x4.shared.b16 {%0,%1,%2,%3}, [%4];"
        : "=r"(r[0]), "=r"(r[1]), "=r"(r[2]), "=r"(r[3]) : "r"(addr));
}
__device__ __forceinline__ void ldsm_x4_t(uint32_t* r, uint32_t addr) {
    asm volatile("ldmatrix.sync.aligned.m8n8.x4.trans.shared.b16 {%0,%1,%2,%3}, [%4];"
        : "=r"(r[0]), "=r"(r[1]), "=r"(r[2]), "=r"(r[3]) : "r"(addr));
}
__device__ __forceinline__ void mma_bf16(float* d, const uint32_t* a, const uint32_t* b) {
    asm volatile("mma.sync.aligned.m16n8k16.row.col.f32.bf16.bf16.f32 "
        "{%0,%1,%2,%3}, {%4,%5,%6,%7}, {%8,%9}, {%0,%1,%2,%3};"
        : "+f"(d[0]), "+f"(d[1]), "+f"(d[2]), "+f"(d[3])
        : "r"(a[0]), "r"(a[1]), "r"(a[2]), "r"(a[3]), "r"(b[0]), "r"(b[1]));
}
__device__ __forceinline__ uint32_t pb2(__nv_bfloat16 a, __nv_bfloat16 b) {
    __nv_bfloat162 t; t.x = a; t.y = b;
    return *(uint32_t*)&t;
}

// ---------------------------------------------------------------------------
// Mega-GEMM: out = tanh(src @ W + bias), bf16 hi/lo split (3 MMAs/term),
// register-prefetch pipeline (R6 scheme), CTA tile 128m x 64n, BK=32,
// 8 warps as 4m x 2n (warp 32x32) -> 288 CTAs = ~2 CTAs/SM.
// smem/buffer: Ahi[128*40] Alo[128*40] Bhi[32*72] Blo[32*72] bf16.
// Blocks: [0,128) H (K=512) | [128,144) A | [144,160) C | [160,288) F (K=128)
// ---------------------------------------------------------------------------
#define A_ELE (128 * 40)
#define B_ELE (32 * 72)
#define BUF_ELE (2 * A_ELE + 2 * B_ELE)     // 14848 bf16
#define GEMM_SMEM (2 * BUF_ELE * 2)         // 59392 bytes

__global__ void __launch_bounds__(256, 2)
megagemm_mma(const float* __restrict__ enc, const float* __restrict__ z,
             const float* __restrict__ outp,
             const float* __restrict__ W1, const float* __restrict__ b1,
             const float* __restrict__ W2, const float* __restrict__ b2,
             const float* __restrict__ W3, const float* __restrict__ b3,
             const float* __restrict__ W4, const float* __restrict__ b4,
             float* __restrict__ H, float* __restrict__ F,
             float* __restrict__ A, float* __restrict__ C)
{
    extern __shared__ __nv_bfloat16 sbuf[];

    int bid = blockIdx.x;
    const float *src, *W, *bias;
    float* dst;
    int K;
    if (bid < 128)      { src = enc;  W = W1; bias = b1; dst = H; K = 512; }
    else if (bid < 144) { src = outp; W = W2; bias = b2; dst = A; K = 512; bid -= 128; }
    else if (bid < 160) { src = outp; W = W4; bias = b4; dst = C; K = 512; bid -= 144; }
    else                { src = z;    W = W3; bias = b3; dst = F; K = 128; bid -= 160; }
    const int nb = bid & 7;          // 512/64 = 8 n-blocks
    const int mb = bid >> 3;
    const int m0 = mb * 128, n0 = nb * 64;

    const int tid  = threadIdx.x;
    const int lane = tid & 31;
    const int wid  = tid >> 5;
    const int wm   = wid & 3;     // 32 m rows
    const int wn   = wid >> 2;    // 32 n cols

    // staging coordinates (R6-style coalesced)
    const int am  = tid >> 3;             // A row base (q*32 offsets)
    const int akq = (tid & 7) * 4;        // A k-quad
    const int bk  = tid >> 3;             // B k-row (0..31)
    const int bnq = (tid & 7) * 8;        // B n-octet

    float acc[2][4][4];
    #pragma unroll
    for (int i = 0; i < 2; i++)
        #pragma unroll
        for (int j = 0; j < 4; j++)
            #pragma unroll
            for (int q = 0; q < 4; q++) acc[i][j][q] = 0.f;

    const int nch = K >> 5;
    float4 ra[4], rb[2];

    // Prologue: load chunk 0
    #pragma unroll
    for (int q = 0; q < 4; q++)
        ra[q] = *(const float4*)&src[(size_t)(m0 + am + q * 32) * K + akq];
    #pragma unroll
    for (int q = 0; q < 2; q++)
        rb[q] = *(const float4*)&W[(size_t)bk * 512 + n0 + bnq + q * 4];

    for (int c = 0; c < nch; c++) {
        const int buf = c & 1;
        __nv_bfloat16* Ahi = sbuf + buf * BUF_ELE;
        __nv_bfloat16* Alo = Ahi + A_ELE;
        __nv_bfloat16* Bhi = Alo + A_ELE;
        __nv_bfloat16* Blo = Bhi + B_ELE;

        // Convert prefetched registers -> smem (hi/lo split)
        #pragma unroll
        for (int q = 0; q < 4; q++) {
            float xs[4] = {ra[q].x, ra[q].y, ra[q].z, ra[q].w};
            __nv_bfloat16 h[4], l[4];
            #pragma unroll
            for (int j = 0; j < 4; j++) {
                h[j] = __float2bfloat16_rn(xs[j]);
                l[j] = __float2bfloat16_rn(xs[j] - __bfloat162float(h[j]));
            }
            uint2 uh; uh.x = pb2(h[0], h[1]); uh.y = pb2(h[2], h[3]);
            uint2 ul; ul.x = pb2(l[0], l[1]); ul.y = pb2(l[2], l[3]);
            *(uint2*)&Ahi[(am + q * 32) * 40 + akq] = uh;
            *(uint2*)&Alo[(am + q * 32) * 40 + akq] = ul;
        }
        #pragma unroll
        for (int q = 0; q < 2; q++) {
            float xs[4] = {rb[q].x, rb[q].y, rb[q].z, rb[q].w};
            __nv_bfloat16 h[4], l[4];
            #pragma unroll
            for (int j = 0; j < 4; j++) {
                h[j] = __float2bfloat16_rn(xs[j]);
                l[j] = __float2bfloat16_rn(xs[j] - __bfloat162float(h[j]));
            }
            uint2 uh; uh.x = pb2(h[0], h[1]); uh.y = pb2(h[2], h[3]);
            uint2 ul; ul.x = pb2(l[0], l[1]); ul.y = pb2(l[2], l[3]);
            *(uint2*)&Bhi[bk * 72 + bnq + q * 4] = uh;
            *(uint2*)&Blo[bk * 72 + bnq + q * 4] = ul;
        }
        __syncthreads();

        // Prefetch next chunk while MMAs run
        if (c + 1 < nch) {
            const int k0g = (c + 1) * 32;
            #pragma unroll
            for (int q = 0; q < 4; q++)
                ra[q] = *(const float4*)&src[(size_t)(m0 + am + q * 32) * K + k0g + akq];
            #pragma unroll
            for (int q = 0; q < 2; q++)
                rb[q] = *(const float4*)&W[(size_t)(k0g + bk) * 512 + n0 + bnq + q * 4];
        }

        const uint32_t aHiB = smem_to_u32(Ahi);
        const uint32_t aLoB = smem_to_u32(Alo);
        const uint32_t bHiB = smem_to_u32(Bhi);
        const uint32_t bLoB = smem_to_u32(Blo);

        #pragma unroll
        for (int ks = 0; ks < 2; ks++) {
            const int k0 = ks * 16;
            uint32_t ah[2][4], al[2][4];
            #pragma unroll
            for (int mi = 0; mi < 2; mi++) {
                int row = wm * 32 + mi * 16 + (lane & 15);
                uint32_t off = (uint32_t)(row * 40 + k0 + (lane >> 4) * 8) * 2;
                ldsm_x4(ah[mi], aHiB + off);
                ldsm_x4(al[mi], aLoB + off);
            }
            #pragma unroll
            for (int nc = 0; nc < 2; nc++) {
                int krow = k0 + (lane & 15);
                int ncol = wn * 32 + nc * 16 + (lane >> 4) * 8;
                uint32_t off = (uint32_t)(krow * 72 + ncol) * 2;
                uint32_t bh[4], bl[4];
                ldsm_x4_t(bh, bHiB + off);
                ldsm_x4_t(bl, bLoB + off);
                #pragma unroll
                for (int mi = 0; mi < 2; mi++) {
                    mma_bf16(acc[mi][nc*2+0], ah[mi], bh);
                    mma_bf16(acc[mi][nc*2+0], al[mi], bh);
                    mma_bf16(acc[mi][nc*2+0], ah[mi], bl);
                    mma_bf16(acc[mi][nc*2+1], ah[mi], bh + 2);
                    mma_bf16(acc[mi][nc*2+1], al[mi], bh + 2);
                    mma_bf16(acc[mi][nc*2+1], ah[mi], bl + 2);
                }
            }
        }
        __syncthreads();
    }

    // Epilogue: bias + tanh + store
    #pragma unroll
    for (int mi = 0; mi < 2; mi++) {
        #pragma unroll
        for (int ni = 0; ni < 4; ni++) {
            int m_g = m0 + wm * 32 + mi * 16 + (lane >> 2);
            int n_g = n0 + wn * 32 + ni * 8 + (lane & 3) * 2;
            float2 bv = *(const float2*)&bias[n_g];
            float2 o0, o1;
            o0.x = tanhf(acc[mi][ni][0] + bv.x);
            o0.y = tanhf(acc[mi][ni][1] + bv.y);
            o1.x = tanhf(acc[mi][ni][2] + bv.x);
            o1.y = tanhf(acc[mi][ni][3] + bv.y);
            *(float2*)&dst[(size_t)m_g * 512 + n_g] = o0;
            *(float2*)&dst[(size_t)(m_g + 8) * 512 + n_g] = o1;
        }
    }
}

// ---------------------------------------------------------------------------
// Dual attention: float4 math + high occupancy via s-split.
// Block = (d-tile 16, b), 512 threads = t(32) x d-quad(4) x s-quarter(4).
// Each thread: thread-local partial softmax over its 64 s; two tiny smem
// reductions merge the 4 s-quarters. tanh-bounded logits -> no max needed.
// smem: 48KB dynamic tiles + 8KB static reduction -> ~2 blocks/SM, 32 warps.
// Grid (32, 8) = 256 blocks.
// ---------------------------------------------------------------------------
__global__ void __launch_bounds__(512)
attn_kernel(const float* __restrict__ H, const float* __restrict__ F,
            const float* __restrict__ Amat, const float* __restrict__ Cmat,
            const float* __restrict__ enc, const float* __restrict__ outp,
            float* __restrict__ concat, float* __restrict__ attn)
{
    extern __shared__ float sm[];
    float* Hs = sm;            // [256][16]
    float* Fs = sm + 4096;     // [256][16]
    float* Es = sm + 8192;     // [256][16]
    __shared__ float4 red[512];

    const int tid = threadIdx.x;
    const int dqi = tid & 3;         // d-quad index
    const int dq  = dqi * 4;
    const int sq  = (tid >> 2) & 3;  // s-quarter
    const int t   = tid >> 4;        // 0..31
    const int d0  = blockIdx.x * 16;
    const int b   = blockIdx.y;

    // Load tiles: 1024 float4 per tile, 512 threads -> 2 iters
    for (int idx = tid; idx < 1024; idx += 512) {
        int s  = idx >> 2;
        int dl = (idx & 3) << 2;
        size_t g = ((size_t)(b * Ss + s)) * Dd + d0 + dl;
        *(float4*)&Hs[s * 16 + dl] = *(const float4*)&H[g];
        *(float4*)&Fs[s * 16 + dl] = *(const float4*)&F[g];
        *(float4*)&Es[s * 16 + dl] = *(const float4*)&enc[g];
    }
    __syncthreads();

    const int m = b * Tt + t;
    const float L2E = 1.4426950408889634f;
    float4 a4 = *(const float4*)&Amat[(size_t)m * Dd + d0 + dq];
    float4 c4 = *(const float4*)&Cmat[(size_t)m * Dd + d0 + dq];
    a4.x *= L2E; a4.y *= L2E; a4.z *= L2E; a4.w *= L2E;
    c4.x *= L2E; c4.y *= L2E; c4.z *= L2E; c4.w *= L2E;

    const int s0 = sq * 64;

    // Pass 1: partial softmax denominators over this s-quarter
    float sx = 0.f, sy = 0.f, sz = 0.f, sw = 0.f;
    #pragma unroll 4
    for (int s = s0; s < s0 + 64; s++) {
        float4 h = *(const float4*)&Hs[s * 16 + dq];
        float4 f = *(const float4*)&Fs[s * 16 + dq];
        sx += exp2f(fmaf(a4.x, h.x, c4.x * f.x));
        sy += exp2f(fmaf(a4.y, h.y, c4.y * f.y));
        sz += exp2f(fmaf(a4.z, h.z, c4.z * f.z));
        sw += exp2f(fmaf(a4.w, h.w, c4.w * f.w));
    }
    red[tid] = make_float4(sx, sy, sz, sw);
    __syncthreads();
    // merge 4 s-quarters (same t, dqi)
    {
        int base = tid & ~12;
        float4 r0 = red[base], r1 = red[base | 4], r2 = red[base | 8], r3 = red[base | 12];
        sx = (r0.x + r1.x) + (r2.x + r3.x);
        sy = (r0.y + r1.y) + (r2.y + r3.y);
        sz = (r0.z + r1.z) + (r2.z + r3.z);
        sw = (r0.w + r1.w) + (r2.w + r3.w);
    }
    const float ix = 1.f / sx, iy = 1.f / sy, iz = 1.f / sz, iw = 1.f / sw;

    // Pass 2: write gamma (STG.128) + partial context
    float cx = 0.f, cy = 0.f, cz = 0.f, cw = 0.f;
    float* ab = attn + (size_t)m * Ss * Dd + d0 + dq;
    #pragma unroll 2
    for (int s = s0; s < s0 + 64; s++) {
        float4 h = *(const float4*)&Hs[s * 16 + dq];
        float4 f = *(const float4*)&Fs[s * 16 + dq];
        float4 e = *(const float4*)&Es[s * 16 + dq];
        float4 gv;
        gv.x = exp2f(fmaf(a4.x, h.x, c4.x * f.x)) * ix;
        gv.y = exp2f(fmaf(a4.y, h.y, c4.y * f.y)) * iy;
        gv.z = exp2f(fmaf(a4.z, h.z, c4.z * f.z)) * iz;
        gv.w = exp2f(fmaf(a4.w, h.w, c4.w * f.w)) * iw;
        *(float4*)&ab[(size_t)s * Dd] = gv;
        cx = fmaf(gv.x, e.x, cx);
        cy = fmaf(gv.y, e.y, cy);
        cz = fmaf(gv.z, e.z, cz);
        cw = fmaf(gv.w, e.w, cw);
    }

    __syncthreads();               // red reuse safety
    red[tid] = make_float4(cx, cy, cz, cw);
    __syncthreads();

    if (sq == 0) {
        int base = tid & ~12;
        float4 r0 = red[base], r1 = red[base | 4], r2 = red[base | 8], r3 = red[base | 12];
        float4 ct;
        ct.x = (r0.x + r1.x) + (r2.x + r3.x);
        ct.y = (r0.y + r1.y) + (r2.y + r3.y);
        ct.z = (r0.z + r1.z) + (r2.z + r3.z);
        ct.w = (r0.w + r1.w) + (r2.w + r3.w);
        *(float4*)&concat[(size_t)m * (2 * Dd) + Dd + d0 + dq] = ct;
    } else if (sq == 1) {
        *(float4*)&concat[(size_t)m * (2 * Dd) + d0 + dq] =
            *(const float4*)&outp[(size_t)m * Dd + d0 + dq];
    }
}

// ---------------------------------------------------------------------------
extern "C" void kernel_launch(void* const* d_in, const int* in_sizes, int n_in,
                              void* d_out, int out_size)
{
    const float* output = (const float*)d_in[0];   // [8,32,512]
    const float* enc    = (const float*)d_in[1];   // [256,8,512] flat [2048,512]
    const float* z      = (const float*)d_in[2];   // [8,256,128] flat [2048,128]
    const float* W1 = (const float*)d_in[3];
    const float* b1 = (const float*)d_in[4];
    const float* W2 = (const float*)d_in[5];
    const float* b2 = (const float*)d_in[6];
    const float* W3 = (const float*)d_in[7];
    const float* b3 = (const float*)d_in[8];
    const float* W4 = (const float*)d_in[9];
    const float* b4 = (const float*)d_in[10];

    float* concat = (float*)d_out;                       // [8,32,1024]
    float* attn   = concat + (size_t)Bb * Tt * 2 * Dd;   // [8,32,256,512]

    float *pH, *pF, *pA, *pC;
    cudaGetSymbolAddress((void**)&pH, g_H);
    cudaGetSymbolAddress((void**)&pF, g_F);
    cudaGetSymbolAddress((void**)&pA, g_A);
    cudaGetSymbolAddress((void**)&pC, g_C);

    cudaFuncSetAttribute(megagemm_mma, cudaFuncAttributeMaxDynamicSharedMemorySize, GEMM_SMEM);
    megagemm_mma<<<288, 256, GEMM_SMEM>>>(enc, z, output,
                                          W1, b1, W2, b2, W3, b3, W4, b4,
                                          pH, pF, pA, pC);

    const int smem_attn = 3 * 4096 * (int)sizeof(float);  // 49152
    cudaFuncSetAttribute(attn_kernel, cudaFuncAttributeMaxDynamicSharedMemorySize, smem_attn);
    attn_kernel<<<dim3(32, Bb), 512, smem_attn>>>(pH, pF, pA, pC, enc, output, concat, attn);
}

// round 11
// speedup vs baseline: 1.0128x; 1.0128x over previous
#include <cuda_runtime.h>
#include <cuda_bf16.h>
#include <math.h>
#include <stdint.h>

#define Bb 8
#define Ss 256
#define Tt 32
#define Dd 512
#define NROWS 2048   // B*S
#define MROWS 256    // B*T

// Scratch (allocation-free rule: __device__ globals)
__device__ float g_H[NROWS * Dd];
__device__ float g_F[NROWS * Dd];
__device__ float g_A[MROWS * Dd];
__device__ float g_C[MROWS * Dd];

// ---------------------------------------------------------------------------
// Warp-MMA helpers (baseline PTX, compiles for plain sm_103)
// ---------------------------------------------------------------------------
__device__ __forceinline__ uint32_t smem_to_u32(const void* p) {
    uint32_t a;
    asm("{ .reg .u64 t; cvta.to.shared.u64 t, %1; cvt.u32.u64 %0, t; }"
        : "=r"(a) : "l"(p));
    return a;
}
__device__ __forceinline__ void ldsm_x4(uint32_t* r, uint32_t addr) {
    asm volatile("ldmatrix.sync.aligned.m8n8.x4.shared.b16 {%0,%1,%2,%3}, [%4];"
        : "=r"(r[0]), "=r"(r[1]), "=r"(r[2]), "=r"(r[3]) : "r"(addr));
}
__device__ __forceinline__ void ldsm_x4_t(uint32_t* r, uint32_t addr) {
    asm volatile("ldmatrix.sync.aligned.m8n8.x4.trans.shared.b16 {%0,%1,%2,%3}, [%4];"
        : "=r"(r[0]), "=r"(r[1]), "=r"(r[2]), "=r"(r[3]) : "r"(addr));
}
__device__ __forceinline__ void mma_bf16(float* d, const uint32_t* a, const uint32_t* b) {
    asm volatile("mma.sync.aligned.m16n8k16.row.col.f32.bf16.bf16.f32 "
        "{%0,%1,%2,%3}, {%4,%5,%6,%7}, {%8,%9}, {%0,%1,%2,%3};"
        : "+f"(d[0]), "+f"(d[1]), "+f"(d[2]), "+f"(d[3])
        : "r"(a[0]), "r"(a[1]), "r"(a[2]), "r"(a[3]), "r"(b[0]), "r"(b[1]));
}
__device__ __forceinline__ uint32_t pb2(__nv_bfloat16 a, __nv_bfloat16 b) {
    __nv_bfloat162 t; t.x = a; t.y = b;
    return *(uint32_t*)&t;
}

// ---------------------------------------------------------------------------
// Mega-GEMM: out = tanh(src @ W + bias), bf16 hi/lo split (3 MMAs/term),
// register-prefetch pipeline (R6 scheme), CTA tile 128m x 64n, BK=32,
// 8 warps as 4m x 2n (warp 32x32) -> 288 CTAs = ~2 CTAs/SM.
// smem/buffer: Ahi[128*40] Alo[128*40] Bhi[32*72] Blo[32*72] bf16.
// Blocks: [0,128) H (K=512) | [128,144) A | [144,160) C | [160,288) F (K=128)
// ---------------------------------------------------------------------------
#define A_ELE (128 * 40)
#define B_ELE (32 * 72)
#define BUF_ELE (2 * A_ELE + 2 * B_ELE)     // 14848 bf16
#define GEMM_SMEM (2 * BUF_ELE * 2)         // 59392 bytes

__global__ void __launch_bounds__(256, 2)
megagemm_mma(const float* __restrict__ enc, const float* __restrict__ z,
             const float* __restrict__ outp,
             const float* __restrict__ W1, const float* __restrict__ b1,
             const float* __restrict__ W2, const float* __restrict__ b2,
             const float* __restrict__ W3, const float* __restrict__ b3,
             const float* __restrict__ W4, const float* __restrict__ b4,
             float* __restrict__ H, float* __restrict__ F,
             float* __restrict__ A, float* __restrict__ C)
{
    extern __shared__ __nv_bfloat16 sbuf[];

    int bid = blockIdx.x;
    const float *src, *W, *bias;
    float* dst;
    int K;
    if (bid < 128)      { src = enc;  W = W1; bias = b1; dst = H; K = 512; }
    else if (bid < 144) { src = outp; W = W2; bias = b2; dst = A; K = 512; bid -= 128; }
    else if (bid < 160) { src = outp; W = W4; bias = b4; dst = C; K = 512; bid -= 144; }
    else                { src = z;    W = W3; bias = b3; dst = F; K = 128; bid -= 160; }
    const int nb = bid & 7;          // 512/64 = 8 n-blocks
    const int mb = bid >> 3;
    const int m0 = mb * 128, n0 = nb * 64;

    const int tid  = threadIdx.x;
    const int lane = tid & 31;
    const int wid  = tid >> 5;
    const int wm   = wid & 3;     // 32 m rows
    const int wn   = wid >> 2;    // 32 n cols

    // staging coordinates (R6-style coalesced)
    const int am  = tid >> 3;             // A row base (q*32 offsets)
    const int akq = (tid & 7) * 4;        // A k-quad
    const int bk  = tid >> 3;             // B k-row (0..31)
    const int bnq = (tid & 7) * 8;        // B n-octet

    float acc[2][4][4];
    #pragma unroll
    for (int i = 0; i < 2; i++)
        #pragma unroll
        for (int j = 0; j < 4; j++)
            #pragma unroll
            for (int q = 0; q < 4; q++) acc[i][j][q] = 0.f;

    const int nch = K >> 5;
    float4 ra[4], rb[2];

    // Prologue: load chunk 0
    #pragma unroll
    for (int q = 0; q < 4; q++)
        ra[q] = *(const float4*)&src[(size_t)(m0 + am + q * 32) * K + akq];
    #pragma unroll
    for (int q = 0; q < 2; q++)
        rb[q] = *(const float4*)&W[(size_t)bk * 512 + n0 + bnq + q * 4];

    for (int c = 0; c < nch; c++) {
        const int buf = c & 1;
        __nv_bfloat16* Ahi = sbuf + buf * BUF_ELE;
        __nv_bfloat16* Alo = Ahi + A_ELE;
        __nv_bfloat16* Bhi = Alo + A_ELE;
        __nv_bfloat16* Blo = Bhi + B_ELE;

        // Convert prefetched registers -> smem (hi/lo split)
        #pragma unroll
        for (int q = 0; q < 4; q++) {
            float xs[4] = {ra[q].x, ra[q].y, ra[q].z, ra[q].w};
            __nv_bfloat16 h[4], l[4];
            #pragma unroll
            for (int j = 0; j < 4; j++) {
                h[j] = __float2bfloat16_rn(xs[j]);
                l[j] = __float2bfloat16_rn(xs[j] - __bfloat162float(h[j]));
            }
            uint2 uh; uh.x = pb2(h[0], h[1]); uh.y = pb2(h[2], h[3]);
            uint2 ul; ul.x = pb2(l[0], l[1]); ul.y = pb2(l[2], l[3]);
            *(uint2*)&Ahi[(am + q * 32) * 40 + akq] = uh;
            *(uint2*)&Alo[(am + q * 32) * 40 + akq] = ul;
        }
        #pragma unroll
        for (int q = 0; q < 2; q++) {
            float xs[4] = {rb[q].x, rb[q].y, rb[q].z, rb[q].w};
            __nv_bfloat16 h[4], l[4];
            #pragma unroll
            for (int j = 0; j < 4; j++) {
                h[j] = __float2bfloat16_rn(xs[j]);
                l[j] = __float2bfloat16_rn(xs[j] - __bfloat162float(h[j]));
            }
            uint2 uh; uh.x = pb2(h[0], h[1]); uh.y = pb2(h[2], h[3]);
            uint2 ul; ul.x = pb2(l[0], l[1]); ul.y = pb2(l[2], l[3]);
            *(uint2*)&Bhi[bk * 72 + bnq + q * 4] = uh;
            *(uint2*)&Blo[bk * 72 + bnq + q * 4] = ul;
        }
        __syncthreads();

        // Prefetch next chunk while MMAs run
        if (c + 1 < nch) {
            const int k0g = (c + 1) * 32;
            #pragma unroll
            for (int q = 0; q < 4; q++)
                ra[q] = *(const float4*)&src[(size_t)(m0 + am + q * 32) * K + k0g + akq];
            #pragma unroll
            for (int q = 0; q < 2; q++)
                rb[q] = *(const float4*)&W[(size_t)(k0g + bk) * 512 + n0 + bnq + q * 4];
        }

        const uint32_t aHiB = smem_to_u32(Ahi);
        const uint32_t aLoB = smem_to_u32(Alo);
        const uint32_t bHiB = smem_to_u32(Bhi);
        const uint32_t bLoB = smem_to_u32(Blo);

        #pragma unroll
        for (int ks = 0; ks < 2; ks++) {
            const int k0 = ks * 16;
            uint32_t ah[2][4], al[2][4];
            #pragma unroll
            for (int mi = 0; mi < 2; mi++) {
                int row = wm * 32 + mi * 16 + (lane & 15);
                uint32_t off = (uint32_t)(row * 40 + k0 + (lane >> 4) * 8) * 2;
                ldsm_x4(ah[mi], aHiB + off);
                ldsm_x4(al[mi], aLoB + off);
            }
            #pragma unroll
            for (int nc = 0; nc < 2; nc++) {
                int krow = k0 + (lane & 15);
                int ncol = wn * 32 + nc * 16 + (lane >> 4) * 8;
                uint32_t off = (uint32_t)(krow * 72 + ncol) * 2;
                uint32_t bh[4], bl[4];
                ldsm_x4_t(bh, bHiB + off);
                ldsm_x4_t(bl, bLoB + off);
                #pragma unroll
                for (int mi = 0; mi < 2; mi++) {
                    mma_bf16(acc[mi][nc*2+0], ah[mi], bh);
                    mma_bf16(acc[mi][nc*2+0], al[mi], bh);
                    mma_bf16(acc[mi][nc*2+0], ah[mi], bl);
                    mma_bf16(acc[mi][nc*2+1], ah[mi], bh + 2);
                    mma_bf16(acc[mi][nc*2+1], al[mi], bh + 2);
                    mma_bf16(acc[mi][nc*2+1], ah[mi], bl + 2);
                }
            }
        }
        __syncthreads();
    }

    // Epilogue: bias + tanh + store
    #pragma unroll
    for (int mi = 0; mi < 2; mi++) {
        #pragma unroll
        for (int ni = 0; ni < 4; ni++) {
            int m_g = m0 + wm * 32 + mi * 16 + (lane >> 2);
            int n_g = n0 + wn * 32 + ni * 8 + (lane & 3) * 2;
            float2 bv = *(const float2*)&bias[n_g];
            float2 o0, o1;
            o0.x = tanhf(acc[mi][ni][0] + bv.x);
            o0.y = tanhf(acc[mi][ni][1] + bv.y);
            o1.x = tanhf(acc[mi][ni][2] + bv.x);
            o1.y = tanhf(acc[mi][ni][3] + bv.y);
            *(float2*)&dst[(size_t)m_g * 512 + n_g] = o0;
            *(float2*)&dst[(size_t)(m_g + 8) * 512 + n_g] = o1;
        }
    }
}

// ---------------------------------------------------------------------------
// Dual attention: float4 math + high occupancy via s-split.
// Block = (d-tile 16, b), 512 threads = t(32) x d-quad(4) x s-quarter(4).
// Each thread: thread-local partial softmax over its 64 s; two tiny smem
// reductions merge the 4 s-quarters. tanh-bounded logits -> no max needed.
// smem: 48KB dynamic tiles + 8KB static reduction -> ~2 blocks/SM, 32 warps.
// Grid (32, 8) = 256 blocks.
// ---------------------------------------------------------------------------
__global__ void __launch_bounds__(512)
attn_kernel(const float* __restrict__ H, const float* __restrict__ F,
            const float* __restrict__ Amat, const float* __restrict__ Cmat,
            const float* __restrict__ enc, const float* __restrict__ outp,
            float* __restrict__ concat, float* __restrict__ attn)
{
    extern __shared__ float sm[];
    float* Hs = sm;            // [256][16]
    float* Fs = sm + 4096;     // [256][16]
    float* Es = sm + 8192;     // [256][16]
    __shared__ float4 red[512];

    const int tid = threadIdx.x;
    const int dqi = tid & 3;         // d-quad index
    const int dq  = dqi * 4;
    const int sq  = (tid >> 2) & 3;  // s-quarter
    const int t   = tid >> 4;        // 0..31
    const int d0  = blockIdx.x * 16;
    const int b   = blockIdx.y;

    // Load tiles: 1024 float4 per tile, 512 threads -> 2 iters
    for (int idx = tid; idx < 1024; idx += 512) {
        int s  = idx >> 2;
        int dl = (idx & 3) << 2;
        size_t g = ((size_t)(b * Ss + s)) * Dd + d0 + dl;
        *(float4*)&Hs[s * 16 + dl] = *(const float4*)&H[g];
        *(float4*)&Fs[s * 16 + dl] = *(const float4*)&F[g];
        *(float4*)&Es[s * 16 + dl] = *(const float4*)&enc[g];
    }
    __syncthreads();

    const int m = b * Tt + t;
    const float L2E = 1.4426950408889634f;
    float4 a4 = *(const float4*)&Amat[(size_t)m * Dd + d0 + dq];
    float4 c4 = *(const float4*)&Cmat[(size_t)m * Dd + d0 + dq];
    a4.x *= L2E; a4.y *= L2E; a4.z *= L2E; a4.w *= L2E;
    c4.x *= L2E; c4.y *= L2E; c4.z *= L2E; c4.w *= L2E;

    const int s0 = sq * 64;

    // Pass 1: partial softmax denominators over this s-quarter
    float sx = 0.f, sy = 0.f, sz = 0.f, sw = 0.f;
    #pragma unroll 4
    for (int s = s0; s < s0 + 64; s++) {
        float4 h = *(const float4*)&Hs[s * 16 + dq];
        float4 f = *(const float4*)&Fs[s * 16 + dq];
        sx += exp2f(fmaf(a4.x, h.x, c4.x * f.x));
        sy += exp2f(fmaf(a4.y, h.y, c4.y * f.y));
        sz += exp2f(fmaf(a4.z, h.z, c4.z * f.z));
        sw += exp2f(fmaf(a4.w, h.w, c4.w * f.w));
    }
    red[tid] = make_float4(sx, sy, sz, sw);
    __syncthreads();
    // merge 4 s-quarters (same t, dqi)
    {
        int base = tid & ~12;
        float4 r0 = red[base], r1 = red[base | 4], r2 = red[base | 8], r3 = red[base | 12];
        sx = (r0.x + r1.x) + (r2.x + r3.x);
        sy = (r0.y + r1.y) + (r2.y + r3.y);
        sz = (r0.z + r1.z) + (r2.z + r3.z);
        sw = (r0.w + r1.w) + (r2.w + r3.w);
    }
    const float ix = 1.f / sx, iy = 1.f / sy, iz = 1.f / sz, iw = 1.f / sw;

    // Pass 2: write gamma (STG.128) + partial context
    float cx = 0.f, cy = 0.f, cz = 0.f, cw = 0.f;
    float* ab = attn + (size_t)m * Ss * Dd + d0 + dq;
    #pragma unroll 2
    for (int s = s0; s < s0 + 64; s++) {
        float4 h = *(const float4*)&Hs[s * 16 + dq];
        float4 f = *(const float4*)&Fs[s * 16 + dq];
        float4 e = *(const float4*)&Es[s * 16 + dq];
        float4 gv;
        gv.x = exp2f(fmaf(a4.x, h.x, c4.x * f.x)) * ix;
        gv.y = exp2f(fmaf(a4.y, h.y, c4.y * f.y)) * iy;
        gv.z = exp2f(fmaf(a4.z, h.z, c4.z * f.z)) * iz;
        gv.w = exp2f(fmaf(a4.w, h.w, c4.w * f.w)) * iw;
        *(float4*)&ab[(size_t)s * Dd] = gv;
        cx = fmaf(gv.x, e.x, cx);
        cy = fmaf(gv.y, e.y, cy);
        cz = fmaf(gv.z, e.z, cz);
        cw = fmaf(gv.w, e.w, cw);
    }

    __syncthreads();               // red reuse safety
    red[tid] = make_float4(cx, cy, cz, cw);
    __syncthreads();

    if (sq == 0) {
        int base = tid & ~12;
        float4 r0 = red[base], r1 = red[base | 4], r2 = red[base | 8], r3 = red[base | 12];
        float4 ct;
        ct.x = (r0.x + r1.x) + (r2.x + r3.x);
        ct.y = (r0.y + r1.y) + (r2.y + r3.y);
        ct.z = (r0.z + r1.z) + (r2.z + r3.z);
        ct.w = (r0.w + r1.w) + (r2.w + r3.w);
        *(float4*)&concat[(size_t)m * (2 * Dd) + Dd + d0 + dq] = ct;
    } else if (sq == 1) {
        *(float4*)&concat[(size_t)m * (2 * Dd) + d0 + dq] =
            *(const float4*)&outp[(size_t)m * Dd + d0 + dq];
    }
}

// ---------------------------------------------------------------------------
extern "C" void kernel_launch(void* const* d_in, const int* in_sizes, int n_in,
                              void* d_out, int out_size)
{
    const float* output = (const float*)d_in[0];   // [8,32,512]
    const float* enc    = (const float*)d_in[1];   // [256,8,512] flat [2048,512]
    const float* z      = (const float*)d_in[2];   // [8,256,128] flat [2048,128]
    const float* W1 = (const float*)d_in[3];
    const float* b1 = (const float*)d_in[4];
    const float* W2 = (const float*)d_in[5];
    const float* b2 = (const float*)d_in[6];
    const float* W3 = (const float*)d_in[7];
    const float* b3 = (const float*)d_in[8];
    const float* W4 = (const float*)d_in[9];
    const float* b4 = (const float*)d_in[10];

    float* concat = (float*)d_out;                       // [8,32,1024]
    float* attn   = concat + (size_t)Bb * Tt * 2 * Dd;   // [8,32,256,512]

    float *pH, *pF, *pA, *pC;
    cudaGetSymbolAddress((void**)&pH, g_H);
    cudaGetSymbolAddress((void**)&pF, g_F);
    cudaGetSymbolAddress((void**)&pA, g_A);
    cudaGetSymbolAddress((void**)&pC, g_C);

    cudaFuncSetAttribute(megagemm_mma, cudaFuncAttributeMaxDynamicSharedMemorySize, GEMM_SMEM);
    megagemm_mma<<<288, 256, GEMM_SMEM>>>(enc, z, output,
                                          W1, b1, W2, b2, W3, b3, W4, b4,
                                          pH, pF, pA, pC);

    const int smem_attn = 3 * 4096 * (int)sizeof(float);  // 49152
    cudaFuncSetAttribute(attn_kernel, cudaFuncAttributeMaxDynamicSharedMemorySize, smem_attn);
    attn_kernel<<<dim3(32, Bb), 512, smem_attn>>>(pH, pF, pA, pC, enc, output, concat, attn);
}

// round 12
// speedup vs baseline: 1.3944x; 1.3768x over previous
#include <cuda_runtime.h>
#include <cuda_fp16.h>
#include <math.h>
#include <stdint.h>

#define Bb 8
#define Ss 256
#define Tt 32
#define Dd 512
#define NROWS 2048   // B*S
#define MROWS 256    // B*T

// Scratch (allocation-free rule: __device__ globals)
__device__ float g_H[NROWS * Dd];
__device__ float g_F[NROWS * Dd];
__device__ float g_A[MROWS * Dd];
__device__ float g_C[MROWS * Dd];

// ---------------------------------------------------------------------------
// Warp-MMA helpers (baseline PTX, compiles for plain sm_103)
// ---------------------------------------------------------------------------
__device__ __forceinline__ uint32_t smem_to_u32(const void* p) {
    uint32_t a;
    asm("{ .reg .u64 t; cvta.to.shared.u64 t, %1; cvt.u32.u64 %0, t; }"
        : "=r"(a) : "l"(p));
    return a;
}
__device__ __forceinline__ void ldsm_x4(uint32_t* r, uint32_t addr) {
    asm volatile("ldmatrix.sync.aligned.m8n8.x4.shared.b16 {%0,%1,%2,%3}, [%4];"
        : "=r"(r[0]), "=r"(r[1]), "=r"(r[2]), "=r"(r[3]) : "r"(addr));
}
__device__ __forceinline__ void ldsm_x4_t(uint32_t* r, uint32_t addr) {
    asm volatile("ldmatrix.sync.aligned.m8n8.x4.trans.shared.b16 {%0,%1,%2,%3}, [%4];"
        : "=r"(r[0]), "=r"(r[1]), "=r"(r[2]), "=r"(r[3]) : "r"(addr));
}
__device__ __forceinline__ void mma_f16(float* d, const uint32_t* a, const uint32_t* b) {
    asm volatile("mma.sync.aligned.m16n8k16.row.col.f32.f16.f16.f32 "
        "{%0,%1,%2,%3}, {%4,%5,%6,%7}, {%8,%9}, {%0,%1,%2,%3};"
        : "+f"(d[0]), "+f"(d[1]), "+f"(d[2]), "+f"(d[3])
        : "r"(a[0]), "r"(a[1]), "r"(a[2]), "r"(a[3]), "r"(b[0]), "r"(b[1]));
}
__device__ __forceinline__ uint32_t pbh(__half a, __half b) {
    __half2 t; t.x = a; t.y = b;
    return *(uint32_t*)&t;
}

// ---------------------------------------------------------------------------
// Mega-GEMM: out = tanh(src @ W + bias).
// fp16 asymmetric split: A = ahi + alo (fp16 split, exact to ~2^-21),
// B = single fp16 plane (err 2^-12 rel) -> 2 MMAs per 16-k group (vs 3
// with bf16 3-term), B staging halved. Register-prefetch pipeline,
// double-buffered smem, one barrier per chunk (R6 proven scheme).
// CTA: 128m x 128n, BK=32, 8 warps as 4m x 2n (warp 32x64). 144 CTAs.
// smem/buffer (halfs): Ahi[128*40] Alo[128*40] Bh[32*136].
// Blocks: [0,64) H (K=512) | [64,72) A | [72,80) C | [80,144) F (K=128 tail)
// ---------------------------------------------------------------------------
#define A_ELE (128 * 40)
#define B_ELE (32 * 136)
#define BUF_ELE (2 * A_ELE + B_ELE)          // 14592 halfs
#define GEMM_SMEM (2 * BUF_ELE * 2)          // 58368 bytes

__global__ void __launch_bounds__(256)
megagemm_mma(const float* __restrict__ enc, const float* __restrict__ z,
             const float* __restrict__ outp,
             const float* __restrict__ W1, const float* __restrict__ b1,
             const float* __restrict__ W2, const float* __restrict__ b2,
             const float* __restrict__ W3, const float* __restrict__ b3,
             const float* __restrict__ W4, const float* __restrict__ b4,
             float* __restrict__ H, float* __restrict__ F,
             float* __restrict__ A, float* __restrict__ C)
{
    extern __shared__ __half sbuf[];

    int bid = blockIdx.x;
    const float *src, *W, *bias;
    float* dst;
    int K;
    if (bid < 64)      { src = enc;  W = W1; bias = b1; dst = H; K = 512; }
    else if (bid < 72) { src = outp; W = W2; bias = b2; dst = A; K = 512; bid -= 64; }
    else if (bid < 80) { src = outp; W = W4; bias = b4; dst = C; K = 512; bid -= 72; }
    else               { src = z;    W = W3; bias = b3; dst = F; K = 128; bid -= 80; }
    const int nb = bid & 3;          // 512/128 = 4 n-blocks
    const int mb = bid >> 2;
    const int m0 = mb * 128, n0 = nb * 128;

    const int tid  = threadIdx.x;
    const int lane = tid & 31;
    const int wid  = tid >> 5;
    const int wm   = wid & 3;     // 32 m rows
    const int wn   = wid >> 2;    // 64 n cols

    // staging coordinates
    const int am  = tid >> 3;             // A row base (+ q*32)
    const int akq = (tid & 7) * 4;        // A k-quad
    const int bk  = tid >> 3;             // B k-row (0..31)
    const int bn  = (tid & 7) * 16;       // B n-base (16 floats per thread)

    float acc[2][8][4];
    #pragma unroll
    for (int i = 0; i < 2; i++)
        #pragma unroll
        for (int j = 0; j < 8; j++)
            #pragma unroll
            for (int q = 0; q < 4; q++) acc[i][j][q] = 0.f;

    const int nch = K >> 5;
    float4 ra[4], rb[4];

    // Prologue: load chunk 0
    #pragma unroll
    for (int q = 0; q < 4; q++)
        ra[q] = *(const float4*)&src[(size_t)(m0 + am + q * 32) * K + akq];
    #pragma unroll
    for (int q = 0; q < 4; q++)
        rb[q] = *(const float4*)&W[(size_t)bk * 512 + n0 + bn + q * 4];

    for (int c = 0; c < nch; c++) {
        const int buf = c & 1;
        __half* Ahi = sbuf + buf * BUF_ELE;
        __half* Alo = Ahi + A_ELE;
        __half* Bh  = Alo + A_ELE;

        // Convert prefetched registers -> smem
        #pragma unroll
        for (int q = 0; q < 4; q++) {
            float xs[4] = {ra[q].x, ra[q].y, ra[q].z, ra[q].w};
            __half h[4], l[4];
            #pragma unroll
            for (int j = 0; j < 4; j++) {
                h[j] = __float2half_rn(xs[j]);
                l[j] = __float2half_rn(xs[j] - __half2float(h[j]));
            }
            uint2 uh; uh.x = pbh(h[0], h[1]); uh.y = pbh(h[2], h[3]);
            uint2 ul; ul.x = pbh(l[0], l[1]); ul.y = pbh(l[2], l[3]);
            *(uint2*)&Ahi[(am + q * 32) * 40 + akq] = uh;
            *(uint2*)&Alo[(am + q * 32) * 40 + akq] = ul;
        }
        #pragma unroll
        for (int q = 0; q < 4; q++) {
            float xs[4] = {rb[q].x, rb[q].y, rb[q].z, rb[q].w};
            uint2 uh;
            uh.x = pbh(__float2half_rn(xs[0]), __float2half_rn(xs[1]));
            uh.y = pbh(__float2half_rn(xs[2]), __float2half_rn(xs[3]));
            *(uint2*)&Bh[bk * 136 + bn + q * 4] = uh;
        }
        __syncthreads();

        // Prefetch next chunk while MMAs run
        if (c + 1 < nch) {
            const int k0g = (c + 1) * 32;
            #pragma unroll
            for (int q = 0; q < 4; q++)
                ra[q] = *(const float4*)&src[(size_t)(m0 + am + q * 32) * K + k0g + akq];
            #pragma unroll
            for (int q = 0; q < 4; q++)
                rb[q] = *(const float4*)&W[(size_t)(k0g + bk) * 512 + n0 + bn + q * 4];
        }

        const uint32_t aHiB = smem_to_u32(Ahi);
        const uint32_t aLoB = smem_to_u32(Alo);
        const uint32_t bHB  = smem_to_u32(Bh);

        #pragma unroll
        for (int ks = 0; ks < 2; ks++) {
            const int k0 = ks * 16;
            uint32_t ah[2][4], al[2][4];
            #pragma unroll
            for (int mi = 0; mi < 2; mi++) {
                int row = wm * 32 + mi * 16 + (lane & 15);
                uint32_t off = (uint32_t)(row * 40 + k0 + (lane >> 4) * 8) * 2;
                ldsm_x4(ah[mi], aHiB + off);
                ldsm_x4(al[mi], aLoB + off);
            }
            #pragma unroll
            for (int nc = 0; nc < 4; nc++) {
                int krow = k0 + (lane & 15);
                int ncol = wn * 64 + nc * 16 + (lane >> 4) * 8;
                uint32_t off = (uint32_t)(krow * 136 + ncol) * 2;
                uint32_t bh[4];
                ldsm_x4_t(bh, bHB + off);
                #pragma unroll
                for (int mi = 0; mi < 2; mi++) {
                    mma_f16(acc[mi][nc*2+0], ah[mi], bh);
                    mma_f16(acc[mi][nc*2+0], al[mi], bh);
                    mma_f16(acc[mi][nc*2+1], ah[mi], bh + 2);
                    mma_f16(acc[mi][nc*2+1], al[mi], bh + 2);
                }
            }
        }
        __syncthreads();
    }

    // Epilogue: bias + tanh + store
    #pragma unroll
    for (int mi = 0; mi < 2; mi++) {
        #pragma unroll
        for (int ni = 0; ni < 8; ni++) {
            int m_g = m0 + wm * 32 + mi * 16 + (lane >> 2);
            int n_g = n0 + wn * 64 + ni * 8 + (lane & 3) * 2;
            float2 bv = *(const float2*)&bias[n_g];
            float2 o0, o1;
            o0.x = tanhf(acc[mi][ni][0] + bv.x);
            o0.y = tanhf(acc[mi][ni][1] + bv.y);
            o1.x = tanhf(acc[mi][ni][2] + bv.x);
            o1.y = tanhf(acc[mi][ni][3] + bv.y);
            *(float2*)&dst[(size_t)m_g * 512 + n_g] = o0;
            *(float2*)&dst[(size_t)(m_g + 8) * 512 + n_g] = o1;
        }
    }
}

// ---------------------------------------------------------------------------
// Barrier-free dual attention (R6 proven optimum: 36.2us).
// Block = (b, d-tile of 32), 1024 threads: thread = (t, single d).
// Thread-local softmax over full s (tanh-bounded logits -> no max needed).
// Warp = one t x 32 consecutive d -> 128B stores, conflict-free smem.
// Grid 128 blocks x 32 warps.
// ---------------------------------------------------------------------------
__global__ void __launch_bounds__(1024)
attn_kernel(const float* __restrict__ H, const float* __restrict__ F,
            const float* __restrict__ Amat, const float* __restrict__ Cmat,
            const float* __restrict__ enc, const float* __restrict__ outp,
            float* __restrict__ concat, float* __restrict__ attn)
{
    extern __shared__ float sm[];
    float* Hs = sm;            // [256][32]
    float* Fs = sm + 8192;     // [256][32]
    float* Es = sm + 16384;    // [256][32]

    const int tid = threadIdx.x;
    const int d   = tid & 31;
    const int t   = tid >> 5;
    const int d0  = blockIdx.x * 32;
    const int b   = blockIdx.y;

    for (int idx = tid; idx < 2048; idx += 1024) {
        int s  = idx >> 3;
        int dl = (idx & 7) << 2;
        size_t g = ((size_t)(b * Ss + s)) * Dd + d0 + dl;
        *(float4*)&Hs[s * 32 + dl] = *(const float4*)&H[g];
        *(float4*)&Fs[s * 32 + dl] = *(const float4*)&F[g];
        *(float4*)&Es[s * 32 + dl] = *(const float4*)&enc[g];
    }
    __syncthreads();

    const int m = b * Tt + t;
    const float L2E = 1.4426950408889634f;
    const float a = Amat[(size_t)m * Dd + d0 + d] * L2E;
    const float c = Cmat[(size_t)m * Dd + d0 + d] * L2E;

    // Pass 1: softmax denominator (thread-local)
    float sum = 0.f;
    #pragma unroll 8
    for (int s = 0; s < Ss; s++)
        sum += exp2f(fmaf(a, Hs[s * 32 + d], c * Fs[s * 32 + d]));
    const float inv = 1.f / sum;

    // Pass 2: write gamma + accumulate context
    float ctx = 0.f;
    float* ab = attn + (size_t)m * Ss * Dd + d0 + d;
    #pragma unroll 4
    for (int s = 0; s < Ss; s++) {
        float g = exp2f(fmaf(a, Hs[s * 32 + d], c * Fs[s * 32 + d])) * inv;
        ab[(size_t)s * Dd] = g;
        ctx = fmaf(g, Es[s * 32 + d], ctx);
    }

    concat[(size_t)m * (2 * Dd) + Dd + d0 + d] = ctx;
    concat[(size_t)m * (2 * Dd) + d0 + d] = outp[(size_t)m * Dd + d0 + d];
}

// ---------------------------------------------------------------------------
extern "C" void kernel_launch(void* const* d_in, const int* in_sizes, int n_in,
                              void* d_out, int out_size)
{
    const float* output = (const float*)d_in[0];   // [8,32,512]
    const float* enc    = (const float*)d_in[1];   // [256,8,512] flat [2048,512]
    const float* z      = (const float*)d_in[2];   // [8,256,128] flat [2048,128]
    const float* W1 = (const float*)d_in[3];
    const float* b1 = (const float*)d_in[4];
    const float* W2 = (const float*)d_in[5];
    const float* b2 = (const float*)d_in[6];
    const float* W3 = (const float*)d_in[7];
    const float* b3 = (const float*)d_in[8];
    const float* W4 = (const float*)d_in[9];
    const float* b4 = (const float*)d_in[10];

    float* concat = (float*)d_out;                       // [8,32,1024]
    float* attn   = concat + (size_t)Bb * Tt * 2 * Dd;   // [8,32,256,512]

    float *pH, *pF, *pA, *pC;
    cudaGetSymbolAddress((void**)&pH, g_H);
    cudaGetSymbolAddress((void**)&pF, g_F);
    cudaGetSymbolAddress((void**)&pA, g_A);
    cudaGetSymbolAddress((void**)&pC, g_C);

    cudaFuncSetAttribute(megagemm_mma, cudaFuncAttributeMaxDynamicSharedMemorySize, GEMM_SMEM);
    megagemm_mma<<<144, 256, GEMM_SMEM>>>(enc, z, output,
                                          W1, b1, W2, b2, W3, b3, W4, b4,
                                          pH, pF, pA, pC);

    const int smem_attn = 3 * 8192 * (int)sizeof(float);  // 98304
    cudaFuncSetAttribute(attn_kernel, cudaFuncAttributeMaxDynamicSharedMemorySize, smem_attn);
    attn_kernel<<<dim3(16, Bb), 1024, smem_attn>>>(pH, pF, pA, pC, enc, output, concat, attn);
}